// round 17
// baseline (speedup 1.0000x reference)
#include <cuda_runtime.h>
#include <stdint.h>

#define BATCH   4
#define NPTS    100000
#define TOTAL   (BATCH * NPTS)
#define D_IN    16
#define D_TOT   19
#define MLP_N   128
#define GRID_X  468
#define GRID_Y  468
#define VOL     (GRID_X * GRID_Y)
#define NVOX    (BATCH * VOL)        // 876096 = 27378 * 32
#define NCHUNK  (NVOX / 32)          // 27378
#define CAP     16
#define FULLM   0xffffffffu

#define THREADS 256
#define BLOCKS  444                  // 3 blocks/SM * 148
#define PAIRS   (BLOCKS * 4)         // 2 warps per pair, 4 pairs per block

__device__ int d_cnt[NVOX];                 // per-voxel count (self-zeroing)
__device__ int d_pidx[(size_t)NVOX * CAP];  // per-voxel point indices

// ---- packed f32x2 helpers (FFMA2, PTX-only) ----
__device__ __forceinline__ unsigned long long dup2(float v) {
    unsigned long long r;
    asm("mov.b64 %0, {%1, %1};" : "=l"(r) : "f"(v));
    return r;
}
__device__ __forceinline__ unsigned long long fma2(unsigned long long a,
                                                   unsigned long long b,
                                                   unsigned long long c) {
    unsigned long long d;
    asm("fma.rn.f32x2 %0, %1, %2, %3;" : "=l"(d) : "l"(a), "l"(b), "l"(c));
    return d;
}
__device__ __forceinline__ void unpack2(unsigned long long p, float& lo, float& hi) {
    asm("mov.b64 {%0, %1}, %2;" : "=f"(lo), "=f"(hi) : "l"(p));
}
__device__ __forceinline__ unsigned long long pack2(float lo, float hi) {
    unsigned long long r;
    asm("mov.b64 %0, {%1, %2};" : "=l"(r) : "f"(lo), "f"(hi));
    return r;
}
__device__ __forceinline__ void prefetchL1(const void* ptr) {
    asm volatile("prefetch.global.L1 [%0];" :: "l"(ptr));
}
__device__ __forceinline__ void pair_barrier(int id) {
    asm volatile("bar.sync %0, 64;" :: "r"(id) : "memory");
}

// ---- K2: bin valid points (per-voxel atomics only) ----
__global__ void __launch_bounds__(256)
bin_points_kernel(const float* __restrict__ xyz,
                  const unsigned int* __restrict__ mask)
{
    const int p = blockIdx.x * blockDim.x + threadIdx.x;
    if (p >= TOTAL) return;
    if (mask[p] == 0u) return;

    const float x = xyz[p * 3 + 0];
    const float y = xyz[p * 3 + 1];
    const float z = xyz[p * 3 + 2];
    const int ivx = (int)floorf(x / 0.32f) + 234;
    const int ivy = (int)floorf(y / 0.32f) + 234;
    const int ivz = (int)floorf(z / 6.0f) + 1;
    if (ivx < 0 || ivx >= GRID_X || ivy < 0 || ivy >= GRID_Y || ivz != 0) return;

    const int batch = p / NPTS;
    const int vid = batch * VOL + ivx * GRID_X + ivy;
    const int slot = atomicAdd(&d_cnt[vid], 1);
    if (slot < CAP) d_pidx[(size_t)vid * CAP + slot] = p;
}

// ---- K3: warp-pair gather. W fully register-resident; ZERO shared memory. ----
// Pair = 2 warps; half h owns output columns [64h, 64h+64) -> 2 cols/lane.
__global__ void __launch_bounds__(THREADS, 3)
gather_kernel(const float* __restrict__ xyz,
              const float* __restrict__ pfeat,
              const float* __restrict__ W,
              const float* __restrict__ bias,
              float* __restrict__ out)
{
    const int lane  = threadIdx.x & 31;
    const int warp  = threadIdx.x >> 5;           // 0..7
    const int half  = warp & 1;
    const int pairb = (warp >> 1) + 1;            // named barrier id 1..4
    const int gpair = blockIdx.x * 4 + (warp >> 1);

    const int colbase = half * 64 + lane * 2;     // this lane's 2 output columns

    // Register-resident W slice: 19 packed f32x2 (38 regs), coalesced float2 loads.
    unsigned long long wreg[D_TOT];
    #pragma unroll
    for (int d = 0; d < D_TOT; ++d) {
        const float2 w = __ldg((const float2*)(W + d * MLP_N + colbase));
        wreg[d] = pack2(w.x, w.y);
    }
    const float2 bb = __ldg((const float2*)(bias + colbase));
    const unsigned long long breg = pack2(bb.x, bb.y);
    const float2 z2 = make_float2(0.f, 0.f);

    int cidx = gpair;
    int c = 0;
    if (cidx < NCHUNK) c = d_cnt[cidx * 32 + lane];
    (void)__ballot_sync(FULLM, c > 0);            // force c landed
    pair_barrier(pairb);                          // both halves have read c

    while (cidx < NCHUNK) {
        const int base = cidx * 32;
        if (half == 0) d_cnt[base + lane] = 0;    // safe: partner read c last iter

        const int nxt = cidx + PAIRS;
        int c1 = 0;
        if (nxt < NCHUNK) c1 = d_cnt[nxt * 32 + lane];

        // lane-parallel first-point index (unconditional: address always in-bounds)
        const int p0 = __ldg(&d_pidx[(size_t)(base + lane) * CAP]);
        if (c > 0) {
            prefetchL1(xyz + (size_t)p0 * 3);
            prefetchL1(pfeat + (size_t)p0 * D_IN);
        }

        #pragma unroll 4
        for (int i = 0; i < 32; ++i) {
            const int ci = __shfl_sync(FULLM, c, i);
            const int v  = base + i;
            float2* dst = (float2*)(out + (size_t)v * MLP_N + colbase);
            if (ci == 0) {                        // warp-uniform
                __stcs(dst, z2);                  // streaming zero (best policy, R11/R15)
                continue;
            }
            const int npt = ci < CAP ? ci : CAP;
            unsigned long long vmax = pack2(-1e30f, -1e30f);

            for (int k = 0; k < npt; ++k) {
                const int pt = (k == 0) ? __shfl_sync(FULLM, p0, i)
                                        : __ldg(&d_pidx[(size_t)v * CAP + k]);
                const float x = xyz[pt * 3 + 0];
                const float y = xyz[pt * 3 + 1];
                const float z = xyz[pt * 3 + 2];
                const float dx = x - floorf(x / 0.32f) * 0.32f;
                const float dy = y - floorf(y / 0.32f) * 0.32f;
                const float dz = z - floorf(z / 6.0f) * 6.0f;

                const float4* f4 = (const float4*)(pfeat + (size_t)pt * D_IN);
                unsigned long long acc = breg;
                #pragma unroll
                for (int g = 0; g < 4; ++g) {     // 16 features, 4 at a time
                    const float4 f = f4[g];
                    acc = fma2(dup2(f.x), wreg[g * 4 + 0], acc);
                    acc = fma2(dup2(f.y), wreg[g * 4 + 1], acc);
                    acc = fma2(dup2(f.z), wreg[g * 4 + 2], acc);
                    acc = fma2(dup2(f.w), wreg[g * 4 + 3], acc);
                }
                acc = fma2(dup2(dx), wreg[16], acc);
                acc = fma2(dup2(dy), wreg[17], acc);
                acc = fma2(dup2(dz), wreg[18], acc);

                float al, ah, ml, mh;
                unpack2(acc, al, ah);
                unpack2(vmax, ml, mh);
                vmax = pack2(fmaxf(ml, al), fmaxf(mh, ah));
            }

            float ml, mh;
            unpack2(vmax, ml, mh);
            // relu monotone: max-then-relu == max-of-relus
            __stcs(dst, make_float2(fmaxf(ml, 0.f), fmaxf(mh, 0.f)));
        }

        (void)__ballot_sync(FULLM, c1 > 0);       // force c1 landed before barrier
        pair_barrier(pairb);                      // partner also landed its c1
        c = c1;
        cidx = nxt;
    }
}

extern "C" void kernel_launch(void* const* d_in, const int* in_sizes, int n_in,
                              void* d_out, int out_size)
{
    const float*        xyz   = (const float*)d_in[0];
    const float*        pfeat = (const float*)d_in[1];
    const unsigned int* mask  = (const unsigned int*)d_in[2];
    const float*        W     = (const float*)d_in[3];
    const float*        bias  = (const float*)d_in[4];
    float*              out   = (float*)d_out;

    // d_cnt starts zeroed (static init) and is re-zeroed by gather_kernel each call.
    bin_points_kernel<<<(TOTAL + 255) / 256, 256>>>(xyz, mask);
    gather_kernel<<<BLOCKS, THREADS>>>(xyz, pfeat, W, bias, out);
}